// round 14
// baseline (speedup 1.0000x reference)
#include <cuda_runtime.h>
#include <cstdint>

#define N_IDX 4096

// Packed meta: bits[0:14)=p00, [14]=dxf, [15]=dyf, [16:20)=wx_q, [20:24)=wy_q
// Weights are EXACT multiples of 1/16 at all levels, so q*(1/16.f) is bit-exact.
__device__ uint32_t g_meta[3 * N_IDX];

__global__ void precompute_meta(const int* __restrict__ indices) {
    int t = blockIdx.x * blockDim.x + threadIdx.x;
    if (t >= 3 * N_IDX) return;
    int lvl = t / N_IDX;
    int j   = t - lvl * N_IDX;
    int H   = 128 >> lvl;
    float scale = (float)H * (1.0f / 256.0f);

    int idx = indices[j];
    int iy = idx >> 8;
    int ix = idx & 255;
    float sy = ((float)iy + 0.5f) * scale - 0.5f;
    float sx = ((float)ix + 0.5f) * scale - 0.5f;
    float y0f = floorf(sy), x0f = floorf(sx);
    float wy = sy - y0f,    wx = sx - x0f;
    int y0 = (int)y0f, x0 = (int)x0f;
    int y0c = min(max(y0,     0), H - 1);
    int y1c = min(max(y0 + 1, 0), H - 1);
    int x0c = min(max(x0,     0), H - 1);
    int x1c = min(max(x0 + 1, 0), H - 1);

    uint32_t wyq = (uint32_t)__float2int_rn(wy * 16.0f);
    uint32_t wxq = (uint32_t)__float2int_rn(wx * 16.0f);
    uint32_t m = (uint32_t)(y0c * H + x0c)
               | ((uint32_t)(x1c - x0c) << 14)
               | ((uint32_t)(y1c - y0c) << 15)
               | (wxq << 16) | (wyq << 20);
    g_meta[t] = m;
}

#define DECODE(m, HSHIFT)                                                     \
    int   p00 = (m) & 0x3fff;                                                 \
    int   dx  = ((m) >> 14) & 1;                                              \
    int   dy  = (((m) >> 15) & 1) << (HSHIFT);                                \
    float wx  = (float)(((m) >> 16) & 15) * 0.0625f;                          \
    float wy  = (float)(((m) >> 20) & 15) * 0.0625f;

#define BUF_FLT 8320   // 33280 B / 4

__device__ __forceinline__ uint32_t smem_u32(const void* p) {
    uint32_t a;
    asm("{ .reg .u64 t; cvta.to.shared.u64 t, %1; cvt.u32.u64 %0, t; }"
        : "=r"(a) : "l"(p));
    return a;
}

// CTA roles, HEAVY-FIRST (grid 2304), each staged tile read ONCE:
//   [0,256)     : f3 — 8 channels interleaved (2x float4 taps, 32KB)
//   [256,768)   : f2 — 2 channels interleaved (float2 taps, 16KB)
//   [768,1280)  : f0 — identity LDG gather, half-plane per CTA
//   [1280,2304) : f1 — 512 planes x 2 row-halves, TMA-staged (33.3KB)
__global__ __launch_bounds__(256, 6) void fused_gather(
    const float* __restrict__ f0, const float* __restrict__ f1,
    const float* __restrict__ f2, const float* __restrict__ f3,
    const int*   __restrict__ indices, float* __restrict__ out)
{
    extern __shared__ float s[];
    int bid = blockIdx.x;
    int tid = threadIdx.x;

    if (bid < 256) {
        // ---- f3: s4[2p], s4[2p+1] = 8 channels of pixel p ----
        int b = bid >> 6, cg = bid & 63;
        int c0 = cg * 8;
        const float* src = f3 + (size_t)(b * 512 + c0) * 1024;
        float4* s4 = (float4*)s;
        #pragma unroll 2
        for (int p = tid; p < 1024; p += 256) {
            float4 a, q;
            a.x = __ldg(src +    0 + p); a.y = __ldg(src + 1024 + p);
            a.z = __ldg(src + 2048 + p); a.w = __ldg(src + 3072 + p);
            q.x = __ldg(src + 4096 + p); q.y = __ldg(src + 5120 + p);
            q.z = __ldg(src + 6144 + p); q.w = __ldg(src + 7168 + p);
            s4[p * 2]     = a;
            s4[p * 2 + 1] = q;
        }
        __syncthreads();

        const uint32_t* meta = g_meta + 2 * N_IDX;
        float* o = out + (size_t)(b * 960 + 448 + c0) * N_IDX;
        for (int j = tid; j < N_IDX; j += 256) {
            uint32_t m = __ldg(meta + j);
            DECODE(m, 5)
            int i00 = 2 * p00, i01 = 2 * (p00 + dx);
            int i10 = 2 * (p00 + dy), i11 = 2 * (p00 + dy + dx);
            float4 a00 = s4[i00], b00 = s4[i00 + 1];
            float4 a01 = s4[i01], b01 = s4[i01 + 1];
            float4 a10 = s4[i10], b10 = s4[i10 + 1];
            float4 a11 = s4[i11], b11 = s4[i11 + 1];
            #define LERP2(v00v, v01v, v10v, v11v, cc)                         \
                { float tp = v00v + wx * (v01v - v00v);                       \
                  float bt = v10v + wx * (v11v - v10v);                       \
                  o[(cc) * N_IDX + j] = tp + wy * (bt - tp); }
            LERP2(a00.x, a01.x, a10.x, a11.x, 0)
            LERP2(a00.y, a01.y, a10.y, a11.y, 1)
            LERP2(a00.z, a01.z, a10.z, a11.z, 2)
            LERP2(a00.w, a01.w, a10.w, a11.w, 3)
            LERP2(b00.x, b01.x, b10.x, b11.x, 4)
            LERP2(b00.y, b01.y, b10.y, b11.y, 5)
            LERP2(b00.z, b01.z, b10.z, b11.z, 6)
            LERP2(b00.w, b01.w, b10.w, b11.w, 7)
            #undef LERP2
        }
    } else if (bid < 768) {
        // ---- f2: s[2p + cc], ILP-2 gather ----
        int rel = bid - 256;
        int b = rel >> 7, cg = rel & 127;
        int c0 = cg * 2;
        const float4* p0 = (const float4*)(f2 + (size_t)(b * 256 + c0) * 4096);
        const float4* p1 = (const float4*)(f2 + (size_t)(b * 256 + c0 + 1) * 4096);
        float4* s4 = (float4*)s;
        #pragma unroll 4
        for (int i = tid; i < 1024; i += 256) {
            float4 a = __ldg(p0 + i), bb = __ldg(p1 + i);
            s4[2 * i]     = make_float4(a.x, bb.x, a.y, bb.y);
            s4[2 * i + 1] = make_float4(a.z, bb.z, a.w, bb.w);
        }
        __syncthreads();

        const uint32_t* meta = g_meta + N_IDX;
        float* o = out + (size_t)(b * 960 + 192 + c0) * N_IDX;
        #pragma unroll
        for (int blk = 0; blk < 8; blk++) {
            int j0 = blk * 512 + tid;
            uint32_t mr[2];
            mr[0] = __ldg(meta + j0);
            mr[1] = __ldg(meta + j0 + 256);
            #pragma unroll
            for (int u = 0; u < 2; u++) {
                DECODE(mr[u], 6)
                float2 v00 = *(const float2*)(s + 2 * p00);
                float2 v01 = *(const float2*)(s + 2 * (p00 + dx));
                float2 v10 = *(const float2*)(s + 2 * (p00 + dy));
                float2 v11 = *(const float2*)(s + 2 * (p00 + dy + dx));
                int j = j0 + u * 256;
                float t0 = v00.x + wx * (v01.x - v00.x);
                float b0 = v10.x + wx * (v11.x - v10.x);
                o[j] = t0 + wy * (b0 - t0);
                float t1 = v00.y + wx * (v01.y - v00.y);
                float b1 = v10.y + wx * (v11.y - v10.y);
                o[N_IDX + j] = t1 + wy * (b1 - t1);
            }
        }
    } else if (bid < 1280) {
        // ---- f0: identity gather, deep MLP ----
        int rel = bid - 768;
        int plane = rel >> 1, half = rel & 1;
        int b = plane >> 6, c = plane & 63;
        const float* pp = f0 + (size_t)plane * 65536;
        float* o = out + (size_t)(b * 960 + c) * N_IDX;
        int j0 = half << 11;
        int idx8[8];
        #pragma unroll
        for (int u = 0; u < 8; u++) idx8[u] = __ldg(indices + j0 + tid + u * 256);
        float v8[8];
        #pragma unroll
        for (int u = 0; u < 8; u++) v8[u] = __ldg(pp + idx8[u]);
        #pragma unroll
        for (int u = 0; u < 8; u++) o[j0 + tid + u * 256] = v8[u];
    } else {
        // ---- f1: TMA bulk staging, row-half per CTA ----
        int rel = bid - 1280;
        int plane = rel >> 1, half = rel & 1;
        int b = plane >> 7, c = plane & 127;
        int r0 = half << 6;
        int bytes = (65 - half) * 512;            // 33280 or 32768
        const float* src = f1 + (size_t)(b * 128 + c) * 16384 + r0 * 128;
        uint32_t mbar = smem_u32(s + BUF_FLT);
        uint32_t dst  = smem_u32(s);
        if (tid == 0)
            asm volatile("mbarrier.init.shared.b64 [%0], 1;" :: "r"(mbar) : "memory");
        __syncthreads();
        if (tid == 0) {
            asm volatile("mbarrier.arrive.expect_tx.shared.b64 _, [%0], %1;"
                         :: "r"(mbar), "r"(bytes) : "memory");
            asm volatile(
                "cp.async.bulk.shared::cta.global.mbarrier::complete_tx::bytes "
                "[%0], [%1], %2, [%3];"
                :: "r"(dst), "l"(src), "r"(bytes), "r"(mbar) : "memory");
        }
        asm volatile(
            "{\n\t.reg .pred P;\n\t"
            "W%=:\n\t"
            "mbarrier.try_wait.parity.acquire.cta.shared::cta.b64 P, [%0], 0, 0x989680;\n\t"
            "@!P bra W%=;\n\t}"
            :: "r"(mbar) : "memory");

        const uint32_t* meta = g_meta;
        float* o = out + (size_t)(b * 960 + 64 + c) * N_IDX;
        int base = r0 << 7;
        #pragma unroll
        for (int blk = 0; blk < 4; blk++) {
            int j0 = blk * 1024 + tid;
            uint32_t mr[4];
            #pragma unroll
            for (int u = 0; u < 4; u++) mr[u] = __ldg(meta + j0 + u * 256);
            #pragma unroll
            for (int u = 0; u < 4; u++) {
                DECODE(mr[u], 7)
                if (((p00 >> 13) & 1) == half) {
                    int sp = p00 - base;
                    float v00 = s[sp];
                    float v01 = s[sp + dx];
                    float v10 = s[sp + dy];
                    float v11 = s[sp + dy + dx];
                    float tp = v00 + wx * (v01 - v00);
                    float bt = v10 + wx * (v11 - v10);
                    o[j0 + u * 256] = tp + wy * (bt - tp);
                }
            }
        }
    }
}

extern "C" void kernel_launch(void* const* d_in, const int* in_sizes, int n_in,
                              void* d_out, int out_size) {
    const float* f0 = nullptr; const float* f1 = nullptr;
    const float* f2 = nullptr; const float* f3 = nullptr;
    const int* indices = nullptr;
    for (int i = 0; i < n_in; i++) {
        switch (in_sizes[i]) {
            case 16777216: f0 = (const float*)d_in[i]; break;
            case 8388608:  f1 = (const float*)d_in[i]; break;
            case 4194304:  f2 = (const float*)d_in[i]; break;
            case 2097152:  f3 = (const float*)d_in[i]; break;
            case N_IDX:    indices = (const int*)d_in[i]; break;
        }
    }
    if (!f0 || !f1 || !f2 || !f3 || !indices) {
        f0 = (const float*)d_in[0];
        f1 = (const float*)d_in[1];
        f2 = (const float*)d_in[2];
        f3 = (const float*)d_in[3];
        indices = (const int*)d_in[4];
    }
    float* out = (float*)d_out;

    precompute_meta<<<(3 * N_IDX + 255) / 256, 256>>>(indices);
    // 33280 B buffer + 16 B mbarrier slot.
    fused_gather<<<2304, 256, 33296>>>(f0, f1, f2, f3, indices, out);
}

// round 15
// speedup vs baseline: 1.3414x; 1.3414x over previous
#include <cuda_runtime.h>
#include <cstdint>

#define N_IDX 4096

// Packed meta: bits[0:14)=p00, [14]=dxf, [15]=dyf, [16:20)=wx_q, [20:24)=wy_q
// Weights are EXACT multiples of 1/16 at all levels, so q*(1/16.f) is bit-exact.
__device__ uint32_t g_meta[3 * N_IDX];

__global__ void precompute_meta(const int* __restrict__ indices) {
    int t = blockIdx.x * blockDim.x + threadIdx.x;
    if (t >= 3 * N_IDX) return;
    int lvl = t / N_IDX;
    int j   = t - lvl * N_IDX;
    int H   = 128 >> lvl;
    float scale = (float)H * (1.0f / 256.0f);

    int idx = indices[j];
    int iy = idx >> 8;
    int ix = idx & 255;
    float sy = ((float)iy + 0.5f) * scale - 0.5f;
    float sx = ((float)ix + 0.5f) * scale - 0.5f;
    float y0f = floorf(sy), x0f = floorf(sx);
    float wy = sy - y0f,    wx = sx - x0f;
    int y0 = (int)y0f, x0 = (int)x0f;
    int y0c = min(max(y0,     0), H - 1);
    int y1c = min(max(y0 + 1, 0), H - 1);
    int x0c = min(max(x0,     0), H - 1);
    int x1c = min(max(x0 + 1, 0), H - 1);

    uint32_t wyq = (uint32_t)__float2int_rn(wy * 16.0f);
    uint32_t wxq = (uint32_t)__float2int_rn(wx * 16.0f);
    uint32_t m = (uint32_t)(y0c * H + x0c)
               | ((uint32_t)(x1c - x0c) << 14)
               | ((uint32_t)(y1c - y0c) << 15)
               | (wxq << 16) | (wyq << 20);
    g_meta[t] = m;
}

#define DECODE(m, HSHIFT)                                                     \
    int   p00 = (m) & 0x3fff;                                                 \
    int   dx  = ((m) >> 14) & 1;                                              \
    int   dy  = (((m) >> 15) & 1) << (HSHIFT);                                \
    float wx  = (float)(((m) >> 16) & 15) * 0.0625f;                          \
    float wy  = (float)(((m) >> 20) & 15) * 0.0625f;

#define BUF_FLT 8320   // 33280 B / 4

__device__ __forceinline__ uint32_t smem_u32(const void* p) {
    uint32_t a;
    asm("{ .reg .u64 t; cvta.to.shared.u64 t, %1; cvt.u32.u64 %0, t; }"
        : "=r"(a) : "l"(p));
    return a;
}

// CTA roles, HEAVY-FIRST (grid 2304), identical per-role code to the 53.6us
// round-11 kernel (launch_bounds(256,5), full ILP), only the order changed:
//   [0,256)     : f3 — 8 channels interleaved (2x float4 taps, 32KB)
//   [256,768)   : f2 — 2 channels interleaved (float2 taps, 16KB, ILP-4)
//   [768,1280)  : f0 — identity LDG gather, half-plane per CTA
//   [1280,2304) : f1 — 512 planes x 2 row-halves, TMA-staged (33.3KB)
__global__ __launch_bounds__(256, 5) void fused_gather(
    const float* __restrict__ f0, const float* __restrict__ f1,
    const float* __restrict__ f2, const float* __restrict__ f3,
    const int*   __restrict__ indices, float* __restrict__ out)
{
    extern __shared__ float s[];
    int bid = blockIdx.x;
    int tid = threadIdx.x;

    if (bid < 256) {
        // ---- f3: s4[2p], s4[2p+1] = 8 channels of pixel p; ILP-1 gather ----
        int b = bid >> 6, cg = bid & 63;
        int c0 = cg * 8;
        const float* src = f3 + (size_t)(b * 512 + c0) * 1024;
        float4* s4 = (float4*)s;
        #pragma unroll 2
        for (int p = tid; p < 1024; p += 256) {
            float4 a, q;
            a.x = __ldg(src +    0 + p); a.y = __ldg(src + 1024 + p);
            a.z = __ldg(src + 2048 + p); a.w = __ldg(src + 3072 + p);
            q.x = __ldg(src + 4096 + p); q.y = __ldg(src + 5120 + p);
            q.z = __ldg(src + 6144 + p); q.w = __ldg(src + 7168 + p);
            s4[p * 2]     = a;
            s4[p * 2 + 1] = q;
        }
        __syncthreads();

        const uint32_t* meta = g_meta + 2 * N_IDX;
        float* o = out + (size_t)(b * 960 + 448 + c0) * N_IDX;
        for (int j = tid; j < N_IDX; j += 256) {
            uint32_t m = __ldg(meta + j);
            DECODE(m, 5)
            int i00 = 2 * p00, i01 = 2 * (p00 + dx);
            int i10 = 2 * (p00 + dy), i11 = 2 * (p00 + dy + dx);
            float4 a00 = s4[i00], b00 = s4[i00 + 1];
            float4 a01 = s4[i01], b01 = s4[i01 + 1];
            float4 a10 = s4[i10], b10 = s4[i10 + 1];
            float4 a11 = s4[i11], b11 = s4[i11 + 1];
            #define LERP2(v00v, v01v, v10v, v11v, cc)                         \
                { float tp = v00v + wx * (v01v - v00v);                       \
                  float bt = v10v + wx * (v11v - v10v);                       \
                  o[(cc) * N_IDX + j] = tp + wy * (bt - tp); }
            LERP2(a00.x, a01.x, a10.x, a11.x, 0)
            LERP2(a00.y, a01.y, a10.y, a11.y, 1)
            LERP2(a00.z, a01.z, a10.z, a11.z, 2)
            LERP2(a00.w, a01.w, a10.w, a11.w, 3)
            LERP2(b00.x, b01.x, b10.x, b11.x, 4)
            LERP2(b00.y, b01.y, b10.y, b11.y, 5)
            LERP2(b00.z, b01.z, b10.z, b11.z, 6)
            LERP2(b00.w, b01.w, b10.w, b11.w, 7)
            #undef LERP2
        }
    } else if (bid < 768) {
        // ---- f2: s[2p + cc], ILP-4 gather (round-11 exact) ----
        int rel = bid - 256;
        int b = rel >> 7, cg = rel & 127;
        int c0 = cg * 2;
        const float4* p0 = (const float4*)(f2 + (size_t)(b * 256 + c0) * 4096);
        const float4* p1 = (const float4*)(f2 + (size_t)(b * 256 + c0 + 1) * 4096);
        float4* s4 = (float4*)s;
        #pragma unroll 4
        for (int i = tid; i < 1024; i += 256) {
            float4 a = __ldg(p0 + i), bb = __ldg(p1 + i);
            s4[2 * i]     = make_float4(a.x, bb.x, a.y, bb.y);
            s4[2 * i + 1] = make_float4(a.z, bb.z, a.w, bb.w);
        }
        __syncthreads();

        const uint32_t* meta = g_meta + N_IDX;
        float* o = out + (size_t)(b * 960 + 192 + c0) * N_IDX;
        #pragma unroll
        for (int blk = 0; blk < 4; blk++) {
            int j0 = blk * 1024 + tid;
            uint32_t mr[4];
            #pragma unroll
            for (int u = 0; u < 4; u++) mr[u] = __ldg(meta + j0 + u * 256);
            #pragma unroll
            for (int u = 0; u < 4; u++) {
                DECODE(mr[u], 6)
                float2 v00 = *(const float2*)(s + 2 * p00);
                float2 v01 = *(const float2*)(s + 2 * (p00 + dx));
                float2 v10 = *(const float2*)(s + 2 * (p00 + dy));
                float2 v11 = *(const float2*)(s + 2 * (p00 + dy + dx));
                int j = j0 + u * 256;
                float t0 = v00.x + wx * (v01.x - v00.x);
                float b0 = v10.x + wx * (v11.x - v10.x);
                o[j] = t0 + wy * (b0 - t0);
                float t1 = v00.y + wx * (v01.y - v00.y);
                float b1 = v10.y + wx * (v11.y - v10.y);
                o[N_IDX + j] = t1 + wy * (b1 - t1);
            }
        }
    } else if (bid < 1280) {
        // ---- f0: identity gather, deep MLP ----
        int rel = bid - 768;
        int plane = rel >> 1, half = rel & 1;
        int b = plane >> 6, c = plane & 63;
        const float* pp = f0 + (size_t)plane * 65536;
        float* o = out + (size_t)(b * 960 + c) * N_IDX;
        int j0 = half << 11;
        int idx8[8];
        #pragma unroll
        for (int u = 0; u < 8; u++) idx8[u] = __ldg(indices + j0 + tid + u * 256);
        float v8[8];
        #pragma unroll
        for (int u = 0; u < 8; u++) v8[u] = __ldg(pp + idx8[u]);
        #pragma unroll
        for (int u = 0; u < 8; u++) o[j0 + tid + u * 256] = v8[u];
    } else {
        // ---- f1: TMA bulk staging, row-half per CTA ----
        int rel = bid - 1280;
        int plane = rel >> 1, half = rel & 1;
        int b = plane >> 7, c = plane & 127;
        int r0 = half << 6;
        int bytes = (65 - half) * 512;            // 33280 or 32768
        const float* src = f1 + (size_t)(b * 128 + c) * 16384 + r0 * 128;
        uint32_t mbar = smem_u32(s + BUF_FLT);
        uint32_t dst  = smem_u32(s);
        if (tid == 0)
            asm volatile("mbarrier.init.shared.b64 [%0], 1;" :: "r"(mbar) : "memory");
        __syncthreads();
        if (tid == 0) {
            asm volatile("mbarrier.arrive.expect_tx.shared.b64 _, [%0], %1;"
                         :: "r"(mbar), "r"(bytes) : "memory");
            asm volatile(
                "cp.async.bulk.shared::cta.global.mbarrier::complete_tx::bytes "
                "[%0], [%1], %2, [%3];"
                :: "r"(dst), "l"(src), "r"(bytes), "r"(mbar) : "memory");
        }
        asm volatile(
            "{\n\t.reg .pred P;\n\t"
            "W%=:\n\t"
            "mbarrier.try_wait.parity.acquire.cta.shared::cta.b64 P, [%0], 0, 0x989680;\n\t"
            "@!P bra W%=;\n\t}"
            :: "r"(mbar) : "memory");

        const uint32_t* meta = g_meta;
        float* o = out + (size_t)(b * 960 + 64 + c) * N_IDX;
        int base = r0 << 7;
        #pragma unroll
        for (int blk = 0; blk < 4; blk++) {
            int j0 = blk * 1024 + tid;
            uint32_t mr[4];
            #pragma unroll
            for (int u = 0; u < 4; u++) mr[u] = __ldg(meta + j0 + u * 256);
            #pragma unroll
            for (int u = 0; u < 4; u++) {
                DECODE(mr[u], 7)
                if (((p00 >> 13) & 1) == half) {
                    int sp = p00 - base;
                    float v00 = s[sp];
                    float v01 = s[sp + dx];
                    float v10 = s[sp + dy];
                    float v11 = s[sp + dy + dx];
                    float tp = v00 + wx * (v01 - v00);
                    float bt = v10 + wx * (v11 - v10);
                    o[j0 + u * 256] = tp + wy * (bt - tp);
                }
            }
        }
    }
}

extern "C" void kernel_launch(void* const* d_in, const int* in_sizes, int n_in,
                              void* d_out, int out_size) {
    const float* f0 = nullptr; const float* f1 = nullptr;
    const float* f2 = nullptr; const float* f3 = nullptr;
    const int* indices = nullptr;
    for (int i = 0; i < n_in; i++) {
        switch (in_sizes[i]) {
            case 16777216: f0 = (const float*)d_in[i]; break;
            case 8388608:  f1 = (const float*)d_in[i]; break;
            case 4194304:  f2 = (const float*)d_in[i]; break;
            case 2097152:  f3 = (const float*)d_in[i]; break;
            case N_IDX:    indices = (const int*)d_in[i]; break;
        }
    }
    if (!f0 || !f1 || !f2 || !f3 || !indices) {
        f0 = (const float*)d_in[0];
        f1 = (const float*)d_in[1];
        f2 = (const float*)d_in[2];
        f3 = (const float*)d_in[3];
        indices = (const int*)d_in[4];
    }
    float* out = (float*)d_out;

    precompute_meta<<<(3 * N_IDX + 255) / 256, 256>>>(indices);
    // 33280 B buffer + 16 B mbarrier slot.
    fused_gather<<<2304, 256, 33296>>>(f0, f1, f2, f3, indices, out);
}